// round 15
// baseline (speedup 1.0000x reference)
#include <cuda_runtime.h>
#include <cstdint>
#include <type_traits>

namespace {

constexpr int LD  = 9;     // 2*lambd+1
constexpr int NP  = 61;    // valid (mu,m1) / (mup,m1p) pairs
constexpr int BLK = 64;    // samples per block
constexpr int THR = 128;   // 2 threads per sample (mup column split)
constexpr int T4  = BLK * 81 / 4;  // 1296 float4 per tile

// Balanced output-column split: FFMA 1891 vs 1830, acc 45 vs 36.
constexpr int MASK0 = 0b100001111;  // mup {0,1,2,3,8}
constexpr int MASK1 = 0b011110000;  // mup {4,5,6,7}

__host__ __device__ constexpr int imax(int a, int b) { return a > b ? a : b; }
__host__ __device__ constexpr int imin(int a, int b) { return a < b ? a : b; }

__host__ __device__ constexpr int lo_m(int m2) { return imax(0, 4 - m2); }
__host__ __device__ constexpr int hi_m(int m2) { return imin(8, 12 - m2); }

__host__ __device__ constexpr int cntmu(int mu) { return 9 - (mu >= 4 ? mu - 4 : 4 - mu); }
__host__ __device__ constexpr int ofsmu(int mu) {
    int o = 0;
    for (int i = 0; i < mu; i++) o += cntmu(i);
    return o;
}
// pair index for (m1,m2): mu-major, m1 ascending (matches reference enumeration)
__host__ __device__ constexpr int pidx(int m1, int m2) {
    int mu   = m1 + m2 - 4;
    int m1lo = imax(0, mu - 4);
    return ofsmu(mu) + (m1 - m1lo);
}

__host__ __device__ constexpr bool inmask(int mask, int mup) { return (mask >> mup) & 1; }
__host__ __device__ constexpr int nmup(int mask) {
    int c = 0;
    for (int i = 0; i < 9; i++) c += (mask >> i) & 1;
    return c;
}
__host__ __device__ constexpr int lmup(int mask, int mup) {
    int c = 0;
    for (int i = 0; i < mup; i++) c += (mask >> i) & 1;
    return c;
}
// g layout restricted to m2p in [lo,hi): q's (ordered m2p-major) whose mup is in mask
__host__ __device__ constexpr int gsizeH(int mask, int lo, int hi) {
    int c = 0;
    for (int m2p = lo; m2p < hi; m2p++)
        for (int m1p = lo_m(m2p); m1p <= hi_m(m2p); m1p++)
            if (inmask(mask, m1p + m2p - 4)) c++;
    return c;
}
__host__ __device__ constexpr int gidxH(int mask, int lo, int hi, int M2P, int M1P) {
    int c = 0;
    for (int m2p = lo; m2p < hi; m2p++)
        for (int m1p = lo_m(m2p); m1p <= hi_m(m2p); m1p++) {
            if (m2p == M2P && m1p == M1P) return c;
            if (inmask(mask, m1p + m2p - 4)) c++;
        }
    return -1;
}

template <int S, int E, class F>
__device__ __forceinline__ void static_for(F&& f) {
    if constexpr (S < E) {
        f(std::integral_constant<int, S>{});
        static_for<S + 1, E>(f);
    }
}

__device__ __forceinline__ uint32_t smem_u32(const void* p) {
    uint32_t a;
    asm("{ .reg .u64 t; cvta.to.shared.u64 t, %1; cvt.u32.u64 %0, t; }" : "=r"(a) : "l"(p));
    return a;
}
// 16B async copy, src_size 0 -> zero-fill (branch-free tail handling)
__device__ __forceinline__ void cp16(uint32_t dst, const float4* src, int sz) {
    asm volatile("cp.async.cg.shared.global [%0], [%1], 16, %2;\n"
                 :: "r"(dst), "l"(src), "r"(sz));
}

// One (m2, m2p-half) pass for a role: builds the half's g (<=16 live regs,
// x2 read directly from smem), then t per valid m1 (register-sourced, no LDS)
// and the FFMAs for this role's mup columns.
template <int MASK, int M2, int LO, int HI, int NM>
__device__ __forceinline__ void half_pass(const float (&x1r)[81],
                                          const float* __restrict__ x2t,
                                          const float* __restrict__ us,
                                          const float* __restrict__ vs,
                                          float (&acc)[9 * NM]) {
    constexpr int GN = gsizeH(MASK, LO, HI);
    float g[GN];
    static_for<LO, HI>([&](auto Jc) {
        constexpr int m2p = decltype(Jc)::value;
        static_for<lo_m(m2p), hi_m(m2p) + 1>([&](auto Ic) {
            constexpr int m1p = decltype(Ic)::value;
            if constexpr (inmask(MASK, m1p + m2p - 4))
                g[gidxH(MASK, LO, HI, m2p, m1p)] =
                    vs[pidx(m1p, m2p)] * x2t[M2 * LD + m2p];
        });
    });
    static_for<lo_m(M2), hi_m(M2) + 1>([&](auto Mc) {
        constexpr int m1 = decltype(Mc)::value;
        const float uu = us[pidx(m1, M2)];
        float t[LD];
        static_for<0, LD>([&](auto Kc) {
            constexpr int k = decltype(Kc)::value;
            t[k] = uu * x1r[m1 * LD + k];          // register source, no LDS
        });
        static_for<LO, HI>([&](auto Jc) {
            constexpr int m2p = decltype(Jc)::value;
            static_for<lo_m(m2p), hi_m(m2p) + 1>([&](auto Ic) {
                constexpr int m1p = decltype(Ic)::value;
                if constexpr (inmask(MASK, m1p + m2p - 4)) {
                    constexpr int mup = m1p + m2p - 4;
                    acc[(m1 + M2 - 4) * NM + lmup(MASK, mup)] +=
                        t[m1p] * g[gidxH(MASK, LO, HI, m2p, m1p)];
                }
            });
        });
    });
}

// One role: this sample's output columns (mup in MASK) for all mu.
// X1 register-resident; g in m2p-halves to cap live registers (~160 total).
template <int MASK>
__device__ __forceinline__ void compute_role(const float (&x1r)[81],
                                             const float* __restrict__ x2t,
                                             const float* __restrict__ us,
                                             const float* __restrict__ vs,
                                             float* __restrict__ stage) {
    constexpr int NM = nmup(MASK);

    float acc[9 * NM];
#pragma unroll
    for (int i = 0; i < 9 * NM; i++) acc[i] = 0.0f;

    static_for<0, LD>([&](auto M2c) {
        constexpr int m2 = decltype(M2c)::value;
        half_pass<MASK, m2, 0, 5, NM>(x1r, x2t, us, vs, acc);
        half_pass<MASK, m2, 5, 9, NM>(x1r, x2t, us, vs, acc);
    });

    // Write this role's disjoint columns into the staging row.
    static_for<0, LD>([&](auto Mc) {
        constexpr int mu = decltype(Mc)::value;
        static_for<0, LD>([&](auto Pc) {
            constexpr int mup = decltype(Pc)::value;
            if constexpr (inmask(MASK, mup))
                stage[mu * LD + mup] = acc[mu * NM + lmup(MASK, mup)];
        });
    });
}

__global__ void __launch_bounds__(THR, 3)
wigner_kernel(const float* __restrict__ X1,
              const float* __restrict__ X2,
              const float* __restrict__ mult,
              float* __restrict__ out, int n) {
    __shared__ __align__(16) float x1s[BLK * 81];
    __shared__ __align__(16) float x2s[BLK * 81];
    __shared__ float us[NP];
    __shared__ float vs[NP];

    const int tid    = threadIdx.x;
    const int lane   = tid & (BLK - 1);   // sample within block
    const int role   = tid >> 6;          // 0: MASK0 columns, 1: MASK1 columns
    const int bstart = blockIdx.x * BLK;

    // Rank-1 refactorization of mult: mult[p*61+q] = c[p]*c[q]
    if (tid < NP) {
        vs[tid] = mult[tid];
        us[tid] = mult[tid * NP] * (1.0f / mult[0]);
    }

    // Stage BOTH tiles via cp.async (independent 16B copies, single wait).
    {
        const int      gbase4 = bstart * 81 / 4;       // bstart*81 % 4 == 0 (BLK=64)
        const int      tot4   = n * 81 / 4;
        const float4*  s1     = reinterpret_cast<const float4*>(X1);
        const float4*  s2     = reinterpret_cast<const float4*>(X2);
        const uint32_t d1     = smem_u32(x1s);
        const uint32_t d2     = smem_u32(x2s);
#pragma unroll
        for (int k = 0; k < (T4 + THR - 1) / THR; k++) {   // 11 slots
            const int idx = k * THR + tid;
            if (idx < T4) {
                const int sz = (gbase4 + idx < tot4) ? 16 : 0;  // tail -> zero-fill
                cp16(d1 + idx * 16, s1 + gbase4 + idx, sz);
                cp16(d2 + idx * 16, s2 + gbase4 + idx, sz);
            }
        }
        asm volatile("cp.async.commit_group;\n");
        asm volatile("cp.async.wait_group 0;\n" ::: "memory");
    }
    __syncthreads();

    // Pull X1 into registers once (81 conflict-free LDS; stride 81 is odd).
    float x1r[81];
    {
        const float* __restrict__ x1t = x1s + lane * 81;
        static_for<0, 81>([&](auto Ic) {
            constexpr int i = decltype(Ic)::value;
            x1r[i] = x1t[i];
        });
    }
    __syncthreads();   // all X1 reads done before x1s is reused for staging

    {
        const float* __restrict__ x2t = x2s + lane * 81;
        float* stage = x1s + lane * 81;   // role partners write disjoint columns
        if (role == 0) compute_role<MASK0>(x1r, x2t, us, vs, stage);
        else           compute_role<MASK1>(x1r, x2t, us, vs, stage);
    }
    __syncthreads();

    // Coalesced float4 writeback of the assembled tile.
    {
        const float4* srcs   = reinterpret_cast<const float4*>(x1s);
        float4*       dsto   = reinterpret_cast<float4*>(out);
        const int     gbase4 = bstart * 81 / 4;
        const int     tot4   = n * 81 / 4;
#pragma unroll
        for (int k = 0; k < (T4 + THR - 1) / THR; k++) {
            const int idx = k * THR + tid;
            if (idx < T4 && gbase4 + idx < tot4) dsto[gbase4 + idx] = srcs[idx];
        }
    }
}

}  // namespace

extern "C" void kernel_launch(void* const* d_in, const int* in_sizes, int n_in,
                              void* d_out, int out_size) {
    const float* X1   = (const float*)d_in[0];
    const float* X2   = (const float*)d_in[1];
    const float* mult = (const float*)d_in[6];
    float*       out  = (float*)d_out;

    const int n      = in_sizes[0] / 81;
    const int blocks = (n + BLK - 1) / BLK;
    wigner_kernel<<<blocks, THR>>>(X1, X2, mult, out, n);
}

// round 16
// speedup vs baseline: 1.3273x; 1.3273x over previous
#include <cuda_runtime.h>
#include <cstdint>
#include <type_traits>

namespace {

constexpr int LD  = 9;     // 2*lambd+1
constexpr int NP  = 61;    // valid (mu,m1) / (mup,m1p) pairs
constexpr int BLK = 32;    // samples per block (small block -> 10 warps/SM at 204 regs)
constexpr int THR = 64;    // 2 threads per sample (mup column split)
constexpr int T4  = BLK * 81 / 4;  // 648 float4 per tile

// Balanced output-column split: FFMA 1891 vs 1830, acc 45 vs 36.
constexpr int MASK0 = 0b100001111;  // mup {0,1,2,3,8}
constexpr int MASK1 = 0b011110000;  // mup {4,5,6,7}

__host__ __device__ constexpr int imax(int a, int b) { return a > b ? a : b; }
__host__ __device__ constexpr int imin(int a, int b) { return a < b ? a : b; }

__host__ __device__ constexpr int lo_m(int m2) { return imax(0, 4 - m2); }
__host__ __device__ constexpr int hi_m(int m2) { return imin(8, 12 - m2); }

__host__ __device__ constexpr int cntmu(int mu) { return 9 - (mu >= 4 ? mu - 4 : 4 - mu); }
__host__ __device__ constexpr int ofsmu(int mu) {
    int o = 0;
    for (int i = 0; i < mu; i++) o += cntmu(i);
    return o;
}
// pair index for (m1,m2): mu-major, m1 ascending (matches reference enumeration)
__host__ __device__ constexpr int pidx(int m1, int m2) {
    int mu   = m1 + m2 - 4;
    int m1lo = imax(0, mu - 4);
    return ofsmu(mu) + (m1 - m1lo);
}

__host__ __device__ constexpr bool inmask(int mask, int mup) { return (mask >> mup) & 1; }
__host__ __device__ constexpr int nmup(int mask) {
    int c = 0;
    for (int i = 0; i < 9; i++) c += (mask >> i) & 1;
    return c;
}
__host__ __device__ constexpr int lmup(int mask, int mup) {
    int c = 0;
    for (int i = 0; i < mup; i++) c += (mask >> i) & 1;
    return c;
}
// role-local g layout: q's (ordered by m2p, m1p) whose mup is in mask
__host__ __device__ constexpr int gsize(int mask) {
    int c = 0;
    for (int m2p = 0; m2p < 9; m2p++)
        for (int m1p = lo_m(m2p); m1p <= hi_m(m2p); m1p++)
            if (inmask(mask, m1p + m2p - 4)) c++;
    return c;
}
__host__ __device__ constexpr int gidx(int mask, int M2P, int M1P) {
    int c = 0;
    for (int m2p = 0; m2p < 9; m2p++)
        for (int m1p = lo_m(m2p); m1p <= hi_m(m2p); m1p++) {
            if (m2p == M2P && m1p == M1P) return c;
            if (inmask(mask, m1p + m2p - 4)) c++;
        }
    return -1;
}

template <int S, int E, class F>
__device__ __forceinline__ void static_for(F&& f) {
    if constexpr (S < E) {
        f(std::integral_constant<int, S>{});
        static_for<S + 1, E>(f);
    }
}

__device__ __forceinline__ uint32_t smem_u32(const void* p) {
    uint32_t a;
    asm("{ .reg .u64 t; cvta.to.shared.u64 t, %1; cvt.u32.u64 %0, t; }" : "=r"(a) : "l"(p));
    return a;
}
// 16B async copy, src_size 0 -> zero-fill (branch-free tail handling)
__device__ __forceinline__ void cp16(uint32_t dst, const float4* src, int sz) {
    asm volatile("cp.async.cg.shared.global [%0], [%1], 16, %2;\n"
                 :: "r"(dst), "l"(src), "r"(sz));
}

// One role: computes this sample's output columns (mup in MASK) for all mu.
// Identical compute structure to R13 (the best-measured stream): X1 register-
// resident, x2 row in registers, full role g (no duplication), t pure FMUL.
template <int MASK>
__device__ __forceinline__ void compute_role(const float (&x1r)[81],
                                             const float* __restrict__ x2t,
                                             const float* __restrict__ us,
                                             const float* __restrict__ vs,
                                             float* __restrict__ stage) {
    constexpr int NM = nmup(MASK);
    constexpr int GN = gsize(MASK);

    float acc[9 * NM];
#pragma unroll
    for (int i = 0; i < 9 * NM; i++) acc[i] = 0.0f;

    static_for<0, LD>([&](auto M2c) {
        constexpr int m2 = decltype(M2c)::value;

        float x2r[LD];
        static_for<0, LD>([&](auto Jc) {
            constexpr int j = decltype(Jc)::value;
            x2r[j] = x2t[m2 * LD + j];                 // conflict-free LDS
        });

        float g[GN];
        static_for<0, LD>([&](auto Jc) {
            constexpr int m2p = decltype(Jc)::value;
            static_for<lo_m(m2p), hi_m(m2p) + 1>([&](auto Ic) {
                constexpr int m1p = decltype(Ic)::value;
                if constexpr (inmask(MASK, m1p + m2p - 4))
                    g[gidx(MASK, m2p, m1p)] = vs[pidx(m1p, m2p)] * x2r[m2p];
            });
        });

        static_for<lo_m(m2), hi_m(m2) + 1>([&](auto Mc) {
            constexpr int m1 = decltype(Mc)::value;
            const float uu = us[pidx(m1, m2)];
            float t[LD];
            static_for<0, LD>([&](auto Kc) {
                constexpr int k = decltype(Kc)::value;
                t[k] = uu * x1r[m1 * LD + k];          // register source, no LDS
            });
            static_for<0, LD>([&](auto Jc) {
                constexpr int m2p = decltype(Jc)::value;
                static_for<lo_m(m2p), hi_m(m2p) + 1>([&](auto Ic) {
                    constexpr int m1p = decltype(Ic)::value;
                    if constexpr (inmask(MASK, m1p + m2p - 4)) {
                        constexpr int mup = m1p + m2p - 4;
                        acc[(m1 + m2 - 4) * NM + lmup(MASK, mup)] +=
                            t[m1p] * g[gidx(MASK, m2p, m1p)];
                    }
                });
            });
        });
    });

    // Write this role's disjoint columns into the staging row.
    static_for<0, LD>([&](auto Mc) {
        constexpr int mu = decltype(Mc)::value;
        static_for<0, LD>([&](auto Pc) {
            constexpr int mup = decltype(Pc)::value;
            if constexpr (inmask(MASK, mup))
                stage[mu * LD + mup] = acc[mu * NM + lmup(MASK, mup)];
        });
    });
}

__global__ void __launch_bounds__(THR, 5)   // 204-reg budget -> 10 warps/SM
wigner_kernel(const float* __restrict__ X1,
              const float* __restrict__ X2,
              const float* __restrict__ mult,
              float* __restrict__ out, int n) {
    __shared__ __align__(16) float x1s[BLK * 81];
    __shared__ __align__(16) float x2s[BLK * 81];
    __shared__ float us[NP];
    __shared__ float vs[NP];

    const int tid    = threadIdx.x;
    const int lane   = tid & (BLK - 1);   // sample within block
    const int role   = tid >> 5;          // warp 0: MASK0, warp 1: MASK1
    const int bstart = blockIdx.x * BLK;

    // Rank-1 refactorization of mult: mult[p*61+q] = c[p]*c[q]
    if (tid < NP) {
        vs[tid] = mult[tid];
        us[tid] = mult[tid * NP] * (1.0f / mult[0]);
    }

    // Stage BOTH tiles via cp.async (independent 16B copies, single wait).
    {
        const int      gbase4 = bstart * 81 / 4;       // bstart*81 % 4 == 0 (BLK=32)
        const int      tot4   = n * 81 / 4;
        const float4*  s1     = reinterpret_cast<const float4*>(X1);
        const float4*  s2     = reinterpret_cast<const float4*>(X2);
        const uint32_t d1     = smem_u32(x1s);
        const uint32_t d2     = smem_u32(x2s);
#pragma unroll
        for (int k = 0; k < (T4 + THR - 1) / THR; k++) {   // 11 slots
            const int idx = k * THR + tid;
            if (idx < T4) {
                const int sz = (gbase4 + idx < tot4) ? 16 : 0;  // tail -> zero-fill
                cp16(d1 + idx * 16, s1 + gbase4 + idx, sz);
                cp16(d2 + idx * 16, s2 + gbase4 + idx, sz);
            }
        }
        asm volatile("cp.async.commit_group;\n");
        asm volatile("cp.async.wait_group 0;\n" ::: "memory");
    }
    __syncthreads();

    // Pull X1 into registers once (81 conflict-free LDS; stride 81 is odd).
    float x1r[81];
    {
        const float* __restrict__ x1t = x1s + lane * 81;
        static_for<0, 81>([&](auto Ic) {
            constexpr int i = decltype(Ic)::value;
            x1r[i] = x1t[i];
        });
    }
    __syncthreads();   // all X1 reads done before x1s is reused for staging

    {
        const float* __restrict__ x2t = x2s + lane * 81;
        float* stage = x1s + lane * 81;   // role partners write disjoint columns
        if (role == 0) compute_role<MASK0>(x1r, x2t, us, vs, stage);
        else           compute_role<MASK1>(x1r, x2t, us, vs, stage);
    }
    __syncthreads();

    // Coalesced float4 writeback of the assembled tile.
    {
        const float4* srcs   = reinterpret_cast<const float4*>(x1s);
        float4*       dsto   = reinterpret_cast<float4*>(out);
        const int     gbase4 = bstart * 81 / 4;
        const int     tot4   = n * 81 / 4;
#pragma unroll
        for (int k = 0; k < (T4 + THR - 1) / THR; k++) {
            const int idx = k * THR + tid;
            if (idx < T4 && gbase4 + idx < tot4) dsto[gbase4 + idx] = srcs[idx];
        }
    }
}

}  // namespace

extern "C" void kernel_launch(void* const* d_in, const int* in_sizes, int n_in,
                              void* d_out, int out_size) {
    const float* X1   = (const float*)d_in[0];
    const float* X2   = (const float*)d_in[1];
    const float* mult = (const float*)d_in[6];
    float*       out  = (float*)d_out;

    const int n      = in_sizes[0] / 81;
    const int blocks = (n + BLK - 1) / BLK;
    wigner_kernel<<<blocks, THR>>>(X1, X2, mult, out, n);
}